// round 1
// baseline (speedup 1.0000x reference)
#include <cuda_runtime.h>

// HybridEulerIntegrator: a_{t+1} = a_t + C * (MLP([x_t, a_t]))^3
// MLP: 2 -> 64 (tanh) -> 1
// Shapes: x [T=2048, B=16384], a0 [B], W1 [2,64], b1 [64], W2 [64,1], b2 [1]
// Output: a [T, B] float32

#define T_STEPS 2048
#define BATCH   16384
#define HIDDEN  64
#define TPE     4    // threads per element
#define UPT     16   // hidden units per thread (HIDDEN / TPE)
#define BLOCK   256

__device__ __forceinline__ float fast_tanh(float v) {
    float y;
    asm("tanh.approx.f32 %0, %1;" : "=f"(y) : "f"(v));
    return y;
}

__global__ void __launch_bounds__(BLOCK)
hybrid_euler_kernel(const float* __restrict__ x,
                    const float* __restrict__ a0,
                    const float* __restrict__ W1,
                    const float* __restrict__ b1,
                    const float* __restrict__ W2,
                    const float* __restrict__ b2,
                    float* __restrict__ out)
{
    const int tid = blockIdx.x * BLOCK + threadIdx.x;
    const int e   = tid >> 2;        // element index (0..BATCH-1)
    const int s   = tid & 3;         // sub-lane within 4-lane group

    // Hoist this thread's 16 hidden-unit weights into registers (loop-invariant).
    float w1x[UPT], w1a[UPT], b1r[UPT], w2r[UPT];
#pragma unroll
    for (int k = 0; k < UPT; k++) {
        const int j = s * UPT + k;
        w1x[k] = W1[j];           // W1[0][j] : weight on x
        w1a[k] = W1[HIDDEN + j];  // W1[1][j] : weight on a
        b1r[k] = b1[j];
        w2r[k] = W2[j];
    }
    const float bias2 = b2[0];

    float a = a0[e];
    const float* xp = x + e;
    float*       op = out + e;

    for (int t = 0; t < T_STEPS; t++) {
        const float xt = __ldg(xp);
        xp += BATCH;

        float dk = 0.0f;
#pragma unroll
        for (int k = 0; k < UPT; k++) {
            float pre = fmaf(xt, w1x[k], fmaf(a, w1a[k], b1r[k]));
            dk = fmaf(fast_tanh(pre), w2r[k], dk);
        }

        // Reduce partial dk across the 4 lanes of this element's group.
        dk += __shfl_xor_sync(0xFFFFFFFFu, dk, 1);
        dk += __shfl_xor_sync(0xFFFFFFFFu, dk, 2);
        dk += bias2;

        // a_new = a + C * dk^3   (dk**3.0 == dk*dk*dk incl. negative dk)
        a = fmaf(0.001f, dk * dk * dk, a);

        if (s == 0) *op = a;
        op += BATCH;
    }
}

extern "C" void kernel_launch(void* const* d_in, const int* in_sizes, int n_in,
                              void* d_out, int out_size)
{
    const float* x  = (const float*)d_in[0];
    const float* a0 = (const float*)d_in[1];
    const float* W1 = (const float*)d_in[2];
    const float* b1 = (const float*)d_in[3];
    const float* W2 = (const float*)d_in[4];
    const float* b2 = (const float*)d_in[5];
    float* out = (float*)d_out;

    const int total_threads = BATCH * TPE;           // 65536
    const int grid = total_threads / BLOCK;          // 256 blocks
    hybrid_euler_kernel<<<grid, BLOCK>>>(x, a0, W1, b1, W2, b2, out);
}

// round 2
// speedup vs baseline: 1.5670x; 1.5670x over previous
#include <cuda_runtime.h>

// HybridEulerIntegrator: a_{t+1} = a_t + C * (MLP([x_t, a_t]))^3
// MLP: 2 -> 64 (tanh) -> 1
// x [2048, 16384], a0 [16384], W1 [2,64], b1 [64], W2 [64,1], b2 [1]
// out: a [2048, 16384] float32

#define T_STEPS 2048
#define BATCH   16384
#define HIDDEN  64
#define TPE     8    // threads per element
#define UPT     8    // hidden units per thread (HIDDEN / TPE)
#define BLOCK   256

__device__ __forceinline__ float fast_tanh(float v) {
    float y;
    asm("tanh.approx.f32 %0, %1;" : "=f"(y) : "f"(v));
    return y;
}

__global__ void __launch_bounds__(BLOCK, 4)
hybrid_euler_kernel(const float* __restrict__ x,
                    const float* __restrict__ a0,
                    const float* __restrict__ W1,
                    const float* __restrict__ b1,
                    const float* __restrict__ W2,
                    const float* __restrict__ b2,
                    float* __restrict__ out)
{
    const int tid = blockIdx.x * BLOCK + threadIdx.x;
    const int e   = tid >> 3;        // element index (0..BATCH-1)
    const int s   = tid & 7;         // sub-lane within 8-lane group

    // Hoist this thread's 8 hidden-unit weights into registers (loop-invariant).
    float w1x[UPT], w1a[UPT], b1r[UPT], w2r[UPT];
#pragma unroll
    for (int k = 0; k < UPT; k++) {
        const int j = s * UPT + k;
        w1x[k] = W1[j];           // W1[0][j] : weight on x
        w1a[k] = W1[HIDDEN + j];  // W1[1][j] : weight on a
        b1r[k] = b1[j];
        w2r[k] = W2[j];
    }
    const float bias2 = b2[0];

    float a = a0[e];
    const float* xp = x + e;
    float*       op = out + e;

    // Software pipeline: x_{t+1} never sits on the a-dependency chain.
    float xt = __ldg(xp);

    for (int t = 0; t < T_STEPS; t++) {
        float xt_next = 0.0f;
        if (t + 1 < T_STEPS) xt_next = __ldg(xp + BATCH);
        xp += BATCH;

        // Two independent accumulation chains (shorter dependency depth).
        float dk0 = 0.0f, dk1 = 0.0f;
#pragma unroll
        for (int k = 0; k < UPT; k += 2) {
            float pre0 = fmaf(xt, w1x[k],     fmaf(a, w1a[k],     b1r[k]));
            float pre1 = fmaf(xt, w1x[k + 1], fmaf(a, w1a[k + 1], b1r[k + 1]));
            dk0 = fmaf(fast_tanh(pre0), w2r[k],     dk0);
            dk1 = fmaf(fast_tanh(pre1), w2r[k + 1], dk1);
        }
        float dk = dk0 + dk1;

        // Reduce partial dk across the 8 lanes of this element's group.
        dk += __shfl_xor_sync(0xFFFFFFFFu, dk, 1);
        dk += __shfl_xor_sync(0xFFFFFFFFu, dk, 2);
        dk += __shfl_xor_sync(0xFFFFFFFFu, dk, 4);
        dk += bias2;

        // a_new = a + C * dk^3   (dk**3.0 == dk*dk*dk incl. negative dk)
        float dk2 = dk * dk;
        a = fmaf(0.001f * dk, dk2, a);

        if (s == 0) *op = a;
        op += BATCH;

        xt = xt_next;
    }
}

extern "C" void kernel_launch(void* const* d_in, const int* in_sizes, int n_in,
                              void* d_out, int out_size)
{
    const float* x  = (const float*)d_in[0];
    const float* a0 = (const float*)d_in[1];
    const float* W1 = (const float*)d_in[2];
    const float* b1 = (const float*)d_in[3];
    const float* W2 = (const float*)d_in[4];
    const float* b2 = (const float*)d_in[5];
    float* out = (float*)d_out;

    const int total_threads = BATCH * TPE;           // 131072
    const int grid = total_threads / BLOCK;          // 512 blocks
    hybrid_euler_kernel<<<grid, BLOCK>>>(x, a0, W1, b1, W2, b2, out);
}

// round 3
// speedup vs baseline: 1.7210x; 1.0983x over previous
#include <cuda_runtime.h>
#include <cuda_fp16.h>

// HybridEulerIntegrator: a_{t+1} = a_t + C * (MLP([x_t, a_t]))^3
// MLP: 2 -> 64 (tanh) -> 1. Hidden layer in packed f16x2 (HFMA2 + tanh.approx.f16x2),
// recurrence state and final reduction kept in f32.
// x [2048, 16384], a0 [16384], W1 [2,64], b1 [64], W2 [64,1], b2 [1]

#define T_STEPS 2048
#define BATCH   16384
#define HIDDEN  64
#define TPE     8    // threads per element
#define PAIRS   4    // half2 pairs per thread (8 hidden units)
#define BLOCK   256
#define W2SCALE 0.125f   // keep f16 accumulator magnitude < ~1

__device__ __forceinline__ __half2 tanh_h2(__half2 v) {
    unsigned r, in = *(unsigned*)&v;
    asm("tanh.approx.f16x2 %0, %1;" : "=r"(r) : "r"(in));
    return *(__half2*)&r;
}

__global__ void __launch_bounds__(BLOCK, 4)
hybrid_euler_kernel(const float* __restrict__ x,
                    const float* __restrict__ a0,
                    const float* __restrict__ W1,
                    const float* __restrict__ b1,
                    const float* __restrict__ W2,
                    const float* __restrict__ b2,
                    float* __restrict__ out)
{
    const int tid = blockIdx.x * BLOCK + threadIdx.x;
    const int e   = tid >> 3;        // element index
    const int s   = tid & 7;         // sub-lane within 8-lane group

    // Pack this thread's 8 hidden units (pairs) into half2 registers.
    __half2 w1x[PAIRS], w1a[PAIRS], b1h[PAIRS], w2h[PAIRS];
#pragma unroll
    for (int p = 0; p < PAIRS; p++) {
        const int j = s * (2 * PAIRS) + 2 * p;
        w1x[p] = __floats2half2_rn(W1[j],           W1[j + 1]);
        w1a[p] = __floats2half2_rn(W1[HIDDEN + j],  W1[HIDDEN + j + 1]);
        b1h[p] = __floats2half2_rn(b1[j],           b1[j + 1]);
        w2h[p] = __floats2half2_rn(W2[j] * W2SCALE, W2[j + 1] * W2SCALE);
    }
    const float bias2 = b2[0];

    float a = a0[e];
    const float* xp = x + e;
    float*       op = out + e;

    // Software pipeline the x stream (independent of the a-chain).
    float xt = __ldg(xp);

    for (int t = 0; t < T_STEPS; t++) {
        float xt_next = 0.0f;
        if (t + 1 < T_STEPS) xt_next = __ldg(xp + BATCH);
        xp += BATCH;

        const __half2 xh = __float2half2_rn(xt);
        const __half2 ah = __float2half2_rn(a);

        // Two independent f16x2 accumulator chains.
        __half2 acc0 = __float2half2_rn(0.0f);
        __half2 acc1 = acc0;
#pragma unroll
        for (int p = 0; p < PAIRS; p += 2) {
            __half2 pre0 = __hfma2(xh, w1x[p],     __hfma2(ah, w1a[p],     b1h[p]));
            __half2 pre1 = __hfma2(xh, w1x[p + 1], __hfma2(ah, w1a[p + 1], b1h[p + 1]));
            acc0 = __hfma2(tanh_h2(pre0), w2h[p],     acc0);
            acc1 = __hfma2(tanh_h2(pre1), w2h[p + 1], acc1);
        }
        const __half2 accs = __hadd2(acc0, acc1);
        float dk = __low2float(accs) + __high2float(accs);

        // Reduce across the 8 lanes of this element's group.
        dk += __shfl_xor_sync(0xFFFFFFFFu, dk, 1);
        dk += __shfl_xor_sync(0xFFFFFFFFu, dk, 2);
        dk += __shfl_xor_sync(0xFFFFFFFFu, dk, 4);
        dk = fmaf(dk, 8.0f, bias2);   // undo W2SCALE, add output bias

        // a += C * dk^3
        const float dk2 = dk * dk;
        a = fmaf(0.001f * dk, dk2, a);

        if (s == 0) *op = a;
        op += BATCH;

        xt = xt_next;
    }
}

extern "C" void kernel_launch(void* const* d_in, const int* in_sizes, int n_in,
                              void* d_out, int out_size)
{
    const float* x  = (const float*)d_in[0];
    const float* a0 = (const float*)d_in[1];
    const float* W1 = (const float*)d_in[2];
    const float* b1 = (const float*)d_in[3];
    const float* W2 = (const float*)d_in[4];
    const float* b2 = (const float*)d_in[5];
    float* out = (float*)d_out;

    const int total_threads = BATCH * TPE;           // 131072
    const int grid = total_threads / BLOCK;          // 512 blocks
    hybrid_euler_kernel<<<grid, BLOCK>>>(x, a0, W1, b1, W2, b2, out);
}